// round 15
// baseline (speedup 1.0000x reference)
#include <cuda_runtime.h>
#include <cstdint>

#define CAPS 32
#define FEAT 256
#define ROW_BYTES (CAPS * FEAT * 4)        // 32768
#define NBUF 2
#define SMEM_BYTES (NBUF * ROW_BYTES + NBUF * 8)   // 2 slots + 2 mbarriers

extern __shared__ unsigned char smem_raw[];

__device__ __forceinline__ uint32_t smem_u32(const void* p) {
    uint32_t a;
    asm("{ .reg .u64 t; cvta.to.shared.u64 t, %1; cvt.u32.u64 %0, t; }"
        : "=r"(a) : "l"(p));
    return a;
}

__device__ __forceinline__ void mbar_init(uint32_t addr, uint32_t count) {
    asm volatile("mbarrier.init.shared::cta.b64 [%0], %1;"
                 :: "r"(addr), "r"(count) : "memory");
}

__device__ __forceinline__ void mbar_expect_tx(uint32_t addr, uint32_t bytes) {
    asm volatile("mbarrier.arrive.expect_tx.shared::cta.b64 _, [%0], %1;"
                 :: "r"(addr), "r"(bytes) : "memory");
}

// Bulk copy with evict-first L2 policy: x is streamed once, keep L2 clean.
__device__ __forceinline__ void bulk_copy_g2s(uint32_t dst, const void* src,
                                              uint32_t bytes, uint32_t mbar) {
    asm volatile(
        "{\n\t"
        ".reg .b64 pol;\n\t"
        "createpolicy.fractional.L2::evict_first.b64 pol, 1.0;\n\t"
        "cp.async.bulk.shared::cta.global.mbarrier::complete_tx::bytes.L2::cache_hint "
        "[%0], [%1], %2, [%3], pol;\n\t"
        "}"
        :: "r"(dst), "l"(src), "r"(bytes), "r"(mbar) : "memory");
}

__device__ __forceinline__ void mbar_wait(uint32_t addr, uint32_t parity) {
    asm volatile(
        "{\n\t"
        ".reg .pred P;\n"
        "WAIT_%=:\n\t"
        "mbarrier.try_wait.parity.acquire.cta.shared::cta.b64 P, [%0], %1, 10000000;\n\t"
        "@!P bra WAIT_%=;\n\t"
        "}"
        :: "r"(addr), "r"(parity) : "memory");
}

__device__ __forceinline__ void stg_cs(float* p, float v) {
    asm volatile("st.global.cs.f32 [%0], %1;" :: "l"(p), "f"(v) : "memory");
}

__global__ __launch_bounds__(256, 3)
void router_kernel(const float* __restrict__ x,
                   const float* __restrict__ bias,
                   float* __restrict__ out, int B)
{
    __shared__ float warp_part[8][32];
    __shared__ float attn8[8][32];      // per-warp private attn row

    const int tid  = threadIdx.x;       // feature column j = tid
    const int lane = tid & 31;
    const int wid  = tid >> 5;
    const int grid = gridDim.x;

    const uint32_t buf_s0    = smem_u32(smem_raw);
    const uint32_t mbar_base = smem_u32(smem_raw + NBUF * ROW_BYTES);

    if (tid == 0) {
        mbar_init(mbar_base,     1);
        mbar_init(mbar_base + 8, 1);
    }
    __syncthreads();

    // bias column j in registers, loaded once per CTA (persistent grid)
    float breg[CAPS];
#pragma unroll
    for (int i = 0; i < CAPS; i++) breg[i] = bias[i * FEAT + tid];

    // Prologue: prefetch first row into slot 0
    if (blockIdx.x < B && tid == 0) {
        mbar_expect_tx(mbar_base, ROW_BYTES);
        bulk_copy_g2s(buf_s0, x + (size_t)blockIdx.x * (CAPS * FEAT),
                      ROW_BYTES, mbar_base);
    }

    uint32_t phase[NBUF] = { 0, 0 };    // constant-indexed -> registers

    for (int b0 = blockIdx.x; b0 < B; b0 += NBUF * grid) {
#pragma unroll
        for (int s = 0; s < NBUF; s++) {
            const int b = b0 + s * grid;
            if (b >= B) continue;

            // Wait for this row's DMA (slot s)
            mbar_wait(mbar_base + s * 8, phase[s]);
            phase[s] ^= 1;

            const float* bp = (const float*)(smem_raw + s * ROW_BYTES) + tid;

            // Load column j; fold t AND the bias dot product cb here
            // (latency-tolerant phase), then square into xv IN PLACE.
            float xv[CAPS];
            float t  = 0.f;
            float cb = 0.f;     // sum_i x[i,j] * bias[i,j]
#pragma unroll
            for (int i = 0; i < CAPS; i++) {
                xv[i] = bp[i * FEAT];
                t += xv[i];
                cb = fmaf(xv[i], breg[i], cb);
            }
#pragma unroll
            for (int i = 0; i < CAPS; i++) xv[i] *= t;

            // Warp transpose-reduce in place: lane l ends with this warp's
            // 32-feature partial of score[l] in xv[0].
#pragma unroll
            for (int d = 16; d >= 1; d >>= 1) {
                const bool up = (lane & d) != 0;
#pragma unroll
                for (int k = 0; k < d; k++) {
                    float send = up ? xv[k] : xv[k + d];
                    float recv = __shfl_xor_sync(0xffffffffu, send, d);
                    xv[k] = (up ? xv[k + d] : xv[k]) + recv;
                }
            }
            warp_part[wid][lane] = xv[0];
            __syncthreads();

            // All threads are now past their previous-iteration reads of
            // slot s^1 -> safe to overwrite it. Prefetch row b+grid.
            const int nb = b + grid;
            if (nb < B && tid == 0) {
                const int ns = s ^ 1;           // compile-time constant
                mbar_expect_tx(mbar_base + ns * 8, ROW_BYTES);
                bulk_copy_g2s(buf_s0 + ns * ROW_BYTES,
                              x + (size_t)nb * (CAPS * FEAT),
                              ROW_BYTES, mbar_base + ns * 8);
            }

            // All warps redundantly compute the 32-wide softmax.
            float sc = 0.f;
#pragma unroll
            for (int w = 0; w < 8; w++) sc += warp_part[w][lane];
            sc *= (1.0f / 16.0f);               // 1/sqrt(FEAT)

            float m = sc;
#pragma unroll
            for (int d = 16; d >= 1; d >>= 1)
                m = fmaxf(m, __shfl_xor_sync(0xffffffffu, m, d));
            float e = __expf(sc - m);
            float sum = e;
#pragma unroll
            for (int d = 16; d >= 1; d >>= 1)
                sum += __shfl_xor_sync(0xffffffffu, sum, d);

            attn8[wid][lane] = e / sum;
            __syncwarp();

            // Epilogue: re-read x column from smem (row still in slot s).
            // out[b,j] = sum_i x[b,i,j]*attn[i] + cb   (bias part prefolded)
            const float* arow = attn8[wid];
            float acc = cb;
#pragma unroll
            for (int i = 0; i < CAPS; i++)
                acc = fmaf(bp[i * FEAT], arow[i], acc);
            stg_cs(out + (size_t)b * FEAT + tid, acc);
        }
    }
}

extern "C" void kernel_launch(void* const* d_in, const int* in_sizes, int n_in,
                              void* d_out, int out_size)
{
    const float* x    = (const float*)d_in[0];   // inputs [B, 32, 256] fp32
    const float* bias = (const float*)d_in[1];   // bias   [32, 256]   fp32
    float* out        = (float*)d_out;           // out    [B, 256]    fp32

    const int B = in_sizes[0] / (CAPS * FEAT);

    cudaFuncSetAttribute(router_kernel,
                         cudaFuncAttributeMaxDynamicSharedMemorySize,
                         SMEM_BYTES);

    int grid = 456;                    // 3 persistent CTAs per SM (152 SMs)
    if (grid > B) grid = B;
    router_kernel<<<grid, 256, SMEM_BYTES>>>(x, bias, out, B);
}

// round 16
// speedup vs baseline: 1.0658x; 1.0658x over previous
#include <cuda_runtime.h>
#include <cstdint>

#define CAPS 32
#define FEAT 256
#define ROW_BYTES (CAPS * FEAT * 4)        // 32768
#define NBUF 2
#define SMEM_BYTES (NBUF * ROW_BYTES + NBUF * 8)   // 2 slots + 2 mbarriers

extern __shared__ unsigned char smem_raw[];

__device__ __forceinline__ uint32_t smem_u32(const void* p) {
    uint32_t a;
    asm("{ .reg .u64 t; cvta.to.shared.u64 t, %1; cvt.u32.u64 %0, t; }"
        : "=r"(a) : "l"(p));
    return a;
}

__device__ __forceinline__ void mbar_init(uint32_t addr, uint32_t count) {
    asm volatile("mbarrier.init.shared::cta.b64 [%0], %1;"
                 :: "r"(addr), "r"(count) : "memory");
}

__device__ __forceinline__ void mbar_expect_tx(uint32_t addr, uint32_t bytes) {
    asm volatile("mbarrier.arrive.expect_tx.shared::cta.b64 _, [%0], %1;"
                 :: "r"(addr), "r"(bytes) : "memory");
}

// Bulk copy with evict-first L2 policy: x is streamed once, keep L2 clean.
__device__ __forceinline__ void bulk_copy_g2s(uint32_t dst, const void* src,
                                              uint32_t bytes, uint32_t mbar) {
    asm volatile(
        "{\n\t"
        ".reg .b64 pol;\n\t"
        "createpolicy.fractional.L2::evict_first.b64 pol, 1.0;\n\t"
        "cp.async.bulk.shared::cta.global.mbarrier::complete_tx::bytes.L2::cache_hint "
        "[%0], [%1], %2, [%3], pol;\n\t"
        "}"
        :: "r"(dst), "l"(src), "r"(bytes), "r"(mbar) : "memory");
}

__device__ __forceinline__ void mbar_wait(uint32_t addr, uint32_t parity) {
    asm volatile(
        "{\n\t"
        ".reg .pred P;\n"
        "WAIT_%=:\n\t"
        "mbarrier.try_wait.parity.acquire.cta.shared::cta.b64 P, [%0], %1, 10000000;\n\t"
        "@!P bra WAIT_%=;\n\t"
        "}"
        :: "r"(addr), "r"(parity) : "memory");
}

__device__ __forceinline__ void stg_cs(float* p, float v) {
    asm volatile("st.global.cs.f32 [%0], %1;" :: "l"(p), "f"(v) : "memory");
}

__global__ __launch_bounds__(256, 3)
void router_kernel(const float* __restrict__ x,
                   const float* __restrict__ bias,
                   float* __restrict__ out, int B)
{
    __shared__ float warp_part[8][32];
    __shared__ float attn8[8][32];      // per-warp private attn row

    const int tid  = threadIdx.x;       // feature column j = tid
    const int lane = tid & 31;
    const int wid  = tid >> 5;
    const int grid = gridDim.x;

    const uint32_t buf_s0    = smem_u32(smem_raw);
    const uint32_t mbar_base = smem_u32(smem_raw + NBUF * ROW_BYTES);

    if (tid == 0) {
        mbar_init(mbar_base,     1);
        mbar_init(mbar_base + 8, 1);
    }
    __syncthreads();

    // bias column j in registers, loaded once per CTA (persistent grid)
    float breg[CAPS];
#pragma unroll
    for (int i = 0; i < CAPS; i++) breg[i] = bias[i * FEAT + tid];

    // Prologue: prefetch first row into slot 0
    if (blockIdx.x < B && tid == 0) {
        mbar_expect_tx(mbar_base, ROW_BYTES);
        bulk_copy_g2s(buf_s0, x + (size_t)blockIdx.x * (CAPS * FEAT),
                      ROW_BYTES, mbar_base);
    }

    uint32_t phase[NBUF] = { 0, 0 };    // constant-indexed -> registers

    for (int b0 = blockIdx.x; b0 < B; b0 += NBUF * grid) {
#pragma unroll
        for (int s = 0; s < NBUF; s++) {
            const int b = b0 + s * grid;
            if (b >= B) continue;

            // Wait for this row's DMA (slot s)
            mbar_wait(mbar_base + s * 8, phase[s]);
            phase[s] ^= 1;

            const float* bp = (const float*)(smem_raw + s * ROW_BYTES) + tid;

            // Load column j; fold t AND the bias dot product cb here
            // (latency-tolerant phase), then square into xv IN PLACE.
            float xv[CAPS];
            float t  = 0.f;
            float cb = 0.f;     // sum_i x[i,j] * bias[i,j]
#pragma unroll
            for (int i = 0; i < CAPS; i++) {
                xv[i] = bp[i * FEAT];
                t += xv[i];
                cb = fmaf(xv[i], breg[i], cb);
            }
#pragma unroll
            for (int i = 0; i < CAPS; i++) xv[i] *= t;

            // Warp transpose-reduce in place: lane l ends with this warp's
            // 32-feature partial of score[l] in xv[0].
#pragma unroll
            for (int d = 16; d >= 1; d >>= 1) {
                const bool up = (lane & d) != 0;
#pragma unroll
                for (int k = 0; k < d; k++) {
                    float send = up ? xv[k] : xv[k + d];
                    float recv = __shfl_xor_sync(0xffffffffu, send, d);
                    xv[k] = (up ? xv[k + d] : xv[k]) + recv;
                }
            }
            warp_part[wid][lane] = xv[0];
            __syncthreads();

            // All threads are now past their previous-iteration reads of
            // slot s^1 -> safe to overwrite it. Prefetch row b+grid.
            const int nb = b + grid;
            if (nb < B && tid == 0) {
                const int ns = s ^ 1;           // compile-time constant
                mbar_expect_tx(mbar_base + ns * 8, ROW_BYTES);
                bulk_copy_g2s(buf_s0 + ns * ROW_BYTES,
                              x + (size_t)nb * (CAPS * FEAT),
                              ROW_BYTES, mbar_base + ns * 8);
            }

            // All warps redundantly compute the 32-wide softmax.
            float sc = 0.f;
#pragma unroll
            for (int w = 0; w < 8; w++) sc += warp_part[w][lane];
            sc *= (1.0f / 16.0f);               // 1/sqrt(FEAT)

            float m = sc;
#pragma unroll
            for (int d = 16; d >= 1; d >>= 1)
                m = fmaxf(m, __shfl_xor_sync(0xffffffffu, m, d));
            float e = __expf(sc - m);
            float sum = e;
#pragma unroll
            for (int d = 16; d >= 1; d >>= 1)
                sum += __shfl_xor_sync(0xffffffffu, sum, d);

            attn8[wid][lane] = e / sum;
            __syncwarp();

            // Epilogue: re-read x column from smem (row still in slot s).
            // out[b,j] = sum_i x[b,i,j]*attn[i] + cb   (bias part prefolded)
            const float* arow = attn8[wid];
            float acc = cb;
#pragma unroll
            for (int i = 0; i < CAPS; i++)
                acc = fmaf(bp[i * FEAT], arow[i], acc);
            stg_cs(out + (size_t)b * FEAT + tid, acc);
        }
    }
}

extern "C" void kernel_launch(void* const* d_in, const int* in_sizes, int n_in,
                              void* d_out, int out_size)
{
    const float* x    = (const float*)d_in[0];   // inputs [B, 32, 256] fp32
    const float* bias = (const float*)d_in[1];   // bias   [32, 256]   fp32
    float* out        = (float*)d_out;           // out    [B, 256]    fp32

    const int B = in_sizes[0] / (CAPS * FEAT);

    cudaFuncSetAttribute(router_kernel,
                         cudaFuncAttributeMaxDynamicSharedMemorySize,
                         SMEM_BYTES);

    int grid = 456;                    // 3 persistent CTAs per SM (152 SMs)
    if (grid > B) grid = B;
    router_kernel<<<grid, 256, SMEM_BYTES>>>(x, bias, out, B);
}